// round 1
// baseline (speedup 1.0000x reference)
#include <cuda_runtime.h>
#include <cuda_fp16.h>
#include <math.h>

// Problem constants
#define BSZ       256
#define NNK       255
#define DIM       128
#define SIGMA_C   0.07f
#define REG_C     0.1f
#define ETA_C     0.001f
#define NITERS    1000

// ---------------- device globals (scratch; no allocations allowed) ----------
__device__ __align__(16) float  g_ftr[2 * BSZ * DIM];     // 512 x 128 normalized features
__device__ __align__(16) float  g_K[BSZ * 2 * BSZ];       // 256 x 512 fp32 kernel matrix
__device__ __align__(16) __half g_KKh[BSZ * BSZ];         // 256 x 256 fp16 copy of K[:, :256]
__device__ __align__(16) float  g_alpha[BSZ * NNK];       // final alpha

// ---------------- P1: feature normalization --------------------------------
// z: (256, 2, 128). nrm over the 2-view axis per (b, d).
__global__ void norm_kernel(const float* __restrict__ z) {
    int b = blockIdx.x;
    int d = threadIdx.x;
    float z0 = z[(b * 2 + 0) * DIM + d];
    float z1 = z[(b * 2 + 1) * DIM + d];
    float n = fmaxf(sqrtf(z0 * z0 + z1 * z1), 1e-12f);
    g_ftr[b * DIM + d]           = z0 / n;
    g_ftr[(BSZ + b) * DIM + d]   = z1 / n;
}

// ---------------- P2: RBF kernel matrix K (256 x 512) ----------------------
__global__ void rbf_kernel_mat() {
    __shared__ float fi[DIM];
    int i = blockIdx.x;
    if (threadIdx.x < DIM) fi[threadIdx.x] = g_ftr[i * DIM + threadIdx.x];
    __syncthreads();
    for (int j = threadIdx.x; j < 2 * BSZ; j += blockDim.x) {
        const float* fj = &g_ftr[j * DIM];
        float d = 0.0f;
        #pragma unroll 8
        for (int c = 0; c < DIM; ++c) {
            float df = fi[c] - fj[c];
            d = fmaf(df, df, d);
        }
        float kv = expf(-SIGMA_C * d);
        g_K[i * (2 * BSZ) + j] = kv;
        if (j < BSZ) g_KKh[i * BSZ + j] = __float2half(kv);
    }
}

// ---------------- P3: persistent PGD kernel --------------------------------
// 128 CTAs, each owns batches (2c, 2c+1). KK fp16 resident in SMEM.
// SMEM layout (bytes):
//   [0, 131072)           half  KK[256][256]
//   +2048                 float ys0[256], ys1[256]
//   +4096                 float Gp0[512], Gp1[512]   (2 m-group partials)
//   +2048                 float row0[256], row1[256] (fp32 KK rows b0, b1)
//   +128                  float wS0[8] wS1[8] wN0[8] wN1[8]
#define PGD_SMEM (131072 + 2048 + 4096 + 2048 + 128)

extern __shared__ char smem_raw[];

__global__ void __launch_bounds__(256, 1)
pgd_kernel(const float* __restrict__ alpha_init) {
    const int tid = threadIdx.x;
    const int b0 = blockIdx.x * 2;
    const int b1 = b0 + 1;

    __half* KKs = (__half*)smem_raw;
    float* ys0  = (float*)(smem_raw + 131072);
    float* ys1  = ys0 + 256;
    float* Gp0  = ys1 + 256;           // 512 floats
    float* Gp1  = Gp0 + 512;           // 512 floats
    float* row0 = Gp1 + 512;
    float* row1 = row0 + 256;
    float* wS0  = row1 + 256;
    float* wS1  = wS0 + 8;
    float* wN0  = wS1 + 8;
    float* wN1  = wN0 + 8;

    // load KK (fp16) into SMEM: 131072 B as float4
    {
        const float4* src = (const float4*)g_KKh;
        float4* dst = (float4*)KKs;
        #pragma unroll
        for (int r = 0; r < 32; ++r) dst[tid + 256 * r] = src[tid + 256 * r];
    }
    // fp32 rows b0, b1 of KK (for the rank-one row_i * S term)
    row0[tid] = g_K[b0 * (2 * BSZ) + tid];
    row1[tid] = g_K[b1 * (2 * BSZ) + tid];

    // init alpha = clip(relu(alpha_init), 0, 1); alpha_prev = alpha
    float a0 = 0.f, ap0 = 0.f, a1 = 0.f, ap1 = 0.f;
    if (tid < NNK) {
        a0 = fminf(fmaxf(alpha_init[b0 * NNK + tid], 0.f), 1.f);
        a1 = fminf(fmaxf(alpha_init[b1 * NNK + tid], 0.f), 1.f);
        ap0 = a0; ap1 = a1;
    }
    const int k0 = tid + (tid >= b0);   // scatter position, batch 0
    const int k1 = tid + (tid >= b1);   // scatter position, batch 1
    const int lane = tid & 31;
    const int wid  = tid >> 5;
    const int t    = tid & 127;         // row-pair owner (rows 2t, 2t+1)
    const int g    = tid >> 7;          // m-half group (0: m<128, 1: m>=128)

    const __half2* kkp = ((const __half2*)KKs) + (size_t)g * 16384 + t;

    __syncthreads();

    for (int it = 0; it < NITERS; ++it) {
        float tf = (float)it;
        float beta = tf / (tf + 3.0f);
        float y0, y1;
        if (tid < NNK) {
            y0 = a0 + beta * (a0 - ap0);
            y1 = a1 + beta * (a1 - ap1);
            ys0[k0] = y0;
            ys1[k1] = y1;
        } else {
            y0 = 0.f; y1 = 0.f;
            ys0[b0] = 0.f;
            ys1[b1] = 0.f;
        }
        // warp-partial sums of y (for S)
        float s0 = y0, s1 = y1;
        #pragma unroll
        for (int off = 16; off; off >>= 1) {
            s0 += __shfl_xor_sync(0xffffffffu, s0, off);
            s1 += __shfl_xor_sync(0xffffffffu, s1, off);
        }
        if (lane == 0) { wS0[wid] = s0; wS1[wid] = s1; }
        __syncthreads();

        // matvec: G[k] = sum_m KK[k][m] * ys[m], using symmetry KK[k][m]=KK[m][k].
        // thread owns rows (2t, 2t+1), m in [128g, 128g+128).
        float2 acc0 = make_float2(0.f, 0.f);
        float2 acc1 = make_float2(0.f, 0.f);
        {
            const float* yp0 = ys0 + g * 128;
            const float* yp1 = ys1 + g * 128;
            #pragma unroll 8
            for (int mm = 0; mm < 128; ++mm) {
                float2 kv = __half22float2(kkp[(size_t)mm * 128]);
                float v0 = yp0[mm];
                float v1 = yp1[mm];
                acc0.x = fmaf(kv.x, v0, acc0.x);
                acc0.y = fmaf(kv.y, v0, acc0.y);
                acc1.x = fmaf(kv.x, v1, acc1.x);
                acc1.y = fmaf(kv.y, v1, acc1.y);
            }
        }
        ((float2*)Gp0)[g * 128 + t] = acc0;
        ((float2*)Gp1)[g * 128 + t] = acc1;
        __syncthreads();

        // gradient assembly + norm
        float S0 = 0.f, S1 = 0.f;
        #pragma unroll
        for (int w = 0; w < 8; ++w) { S0 += wS0[w]; S1 += wS1[w]; }

        float gv0 = 0.f, gv1 = 0.f;
        if (tid < NNK) {
            float G0k = Gp0[k0] + Gp0[256 + k0];
            float G1k = Gp1[k1] + Gp1[256 + k1];
            float G0b = Gp0[b0] + Gp0[256 + b0];
            float G1b = Gp1[b1] + Gp1[256 + b1];
            gv0 = S0 + REG_C * y0 + G0k - row0[k0] * S0 - G0b - 2.0f;
            gv1 = S1 + REG_C * y1 + G1k - row1[k1] * S1 - G1b - 2.0f;
        }
        float n0 = gv0 * gv0, n1 = gv1 * gv1;
        #pragma unroll
        for (int off = 16; off; off >>= 1) {
            n0 += __shfl_xor_sync(0xffffffffu, n0, off);
            n1 += __shfl_xor_sync(0xffffffffu, n1, off);
        }
        if (lane == 0) { wN0[wid] = n0; wN1[wid] = n1; }
        __syncthreads();

        float N0 = 0.f, N1 = 0.f;
        #pragma unroll
        for (int w = 0; w < 8; ++w) { N0 += wN0[w]; N1 += wN1[w]; }
        float inv0 = 1.0f / (sqrtf(N0) + 1e-12f);
        float inv1 = 1.0f / (sqrtf(N1) + 1e-12f);

        if (tid < NNK) {
            float an0 = fminf(fmaxf(y0 - ETA_C * gv0 * inv0, 0.f), 1.f);
            float an1 = fminf(fmaxf(y1 - ETA_C * gv1 * inv1, 0.f), 1.f);
            ap0 = a0; a0 = an0;
            ap1 = a1; a1 = an1;
        }
    }

    if (tid < NNK) {
        g_alpha[b0 * NNK + tid] = a0;
        g_alpha[b1 * NNK + tid] = a1;
    }
}

// ---------------- P4: epilogue (loss + stats) -------------------------------
__device__ __forceinline__ float block_sum_256(float v, float* red, int tid) {
    red[tid] = v;
    __syncthreads();
    #pragma unroll
    for (int s = 128; s > 0; s >>= 1) {
        if (tid < s) red[tid] += red[tid + s];
        __syncthreads();
    }
    float r = red[0];
    __syncthreads();
    return r;
}

__global__ void post_kernel(float* __restrict__ out) {
    __shared__ float red[256];
    int b = threadIdx.x;   // one thread per batch

    float ax = 0.f, negs = 0.f, knts = 0.f;
    float c1 = 0.f, cpos = 0.f, c0 = 0.f;
    for (int i = 0; i < NNK; ++i) {
        float a = g_alpha[b * NNK + i];
        int k = i + (i >= b);
        float knt = g_K[k * (2 * BSZ) + BSZ + b];   // Ks[k][b] = K[k, 256+b]
        ax   += a;
        negs += a * knt;
        knts += knt;
        c1   += (a == 1.0f) ? 1.f : 0.f;
        cpos += (a >  0.0f) ? 1.f : 0.f;
        c0   += (a == 0.0f) ? 1.f : 0.f;
    }
    float pos = g_K[b * (2 * BSZ) + BSZ + b];       // diag(Ks)

    float S_axpos = block_sum_256(ax * pos, red, b);
    float S_negs  = block_sum_256(negs,    red, b);
    float S_pos   = block_sum_256(pos,     red, b);
    float S_knts  = block_sum_256(knts,    red, b);
    float S_c1    = block_sum_256(c1,      red, b);
    float S_cpos  = block_sum_256(cpos,    red, b);
    float S_c0    = block_sum_256(c0,      red, b);

    if (b == 0) {
        float pos_loss = S_axpos / (float)BSZ;
        float neg_loss = S_negs / (float)BSZ;
        out[0] = neg_loss - pos_loss;
        out[1] = S_pos / (float)BSZ;
        out[2] = S_knts / ((float)BSZ * (float)NNK);
        out[3] = S_c1 / (S_cpos + 1e-10f);
        out[4] = S_c0 / ((float)BSZ * (float)NNK);
        out[5] = 0.0f;
    }
}

// ---------------- launch ----------------------------------------------------
extern "C" void kernel_launch(void* const* d_in, const int* in_sizes, int n_in,
                              void* d_out, int out_size) {
    const float* z  = (const float*)d_in[0];
    const float* ai = (const float*)d_in[1];
    // defensive: disambiguate by element counts (z=65536, alpha_init=65280)
    if (n_in >= 2 && in_sizes[0] == BSZ * NNK && in_sizes[1] == BSZ * 2 * DIM) {
        const float* tmp = z; z = ai; ai = tmp;
    }

    cudaFuncSetAttribute(pgd_kernel,
                         cudaFuncAttributeMaxDynamicSharedMemorySize, PGD_SMEM);

    norm_kernel<<<BSZ, DIM>>>(z);
    rbf_kernel_mat<<<BSZ, 256>>>();
    pgd_kernel<<<BSZ / 2, 256, PGD_SMEM>>>(ai);
    post_kernel<<<1, 256>>>((float*)d_out);
}

// round 3
// speedup vs baseline: 2.1806x; 2.1806x over previous
#include <cuda_runtime.h>
#include <cuda_fp16.h>
#include <math.h>
#include <stdint.h>

// Problem constants
#define BSZ       256
#define NNK       255
#define DIM       128
#define SIGMA_C   0.07f
#define REG_C     0.1f
#define ETA_C     0.001f
#define NITERS    1000

// ---------------- device globals (scratch; no allocations allowed) ----------
__device__ __align__(16) float g_ftr[2 * BSZ * DIM];   // 512 x 128 normalized features
__device__ __align__(16) float g_K[BSZ * 2 * BSZ];     // 256 x 512 fp32 kernel matrix
__device__ __align__(16) float g_partial[BSZ * 8];     // per-batch stats partials

// ---------------- P1: feature normalization --------------------------------
__global__ void norm_kernel(const float* __restrict__ z) {
    int b = blockIdx.x;
    int d = threadIdx.x;
    float z0 = z[(b * 2 + 0) * DIM + d];
    float z1 = z[(b * 2 + 1) * DIM + d];
    float n = fmaxf(sqrtf(z0 * z0 + z1 * z1), 1e-12f);
    g_ftr[b * DIM + d]         = z0 / n;
    g_ftr[(BSZ + b) * DIM + d] = z1 / n;
}

// ---------------- P2: RBF kernel matrix K (256 x 512) ----------------------
__global__ void rbf_kernel_mat() {
    __shared__ float fi[DIM];
    int i = blockIdx.x;
    if (threadIdx.x < DIM) fi[threadIdx.x] = g_ftr[i * DIM + threadIdx.x];
    __syncthreads();
    for (int j = threadIdx.x; j < 2 * BSZ; j += blockDim.x) {
        const float* fj = &g_ftr[j * DIM];
        float d = 0.0f;
        #pragma unroll 8
        for (int c = 0; c < DIM; ++c) {
            float df = fi[c] - fj[c];
            d = fmaf(df, df, d);
        }
        g_K[i * (2 * BSZ) + j] = expf(-SIGMA_C * d);
    }
}

// ---------------- HMMA helper ------------------------------------------------
__device__ __forceinline__ void mma16816(float* d, const uint32_t* a,
                                         uint32_t b0, uint32_t b1) {
    asm volatile(
        "mma.sync.aligned.m16n8k16.row.col.f32.f16.f16.f32 "
        "{%0,%1,%2,%3}, {%4,%5,%6,%7}, {%8,%9}, {%0,%1,%2,%3};"
        : "+f"(d[0]), "+f"(d[1]), "+f"(d[2]), "+f"(d[3])
        : "r"(a[0]), "r"(a[1]), "r"(a[2]), "r"(a[3]), "r"(b0), "r"(b1));
}

__device__ __forceinline__ uint32_t packh2(float lo, float hi) {
    __half2 h = __floats2half2_rn(lo, hi);
    return *(uint32_t*)&h;
}

__device__ __forceinline__ float blkred(float v, volatile float* scr, int tid) {
    scr[tid] = v;
    __syncthreads();
    #pragma unroll
    for (int s = 128; s > 0; s >>= 1) {
        if (tid < s) scr[tid] = scr[tid] + scr[tid + s];
        __syncthreads();
    }
    float r = scr[0];
    __syncthreads();
    return r;
}

// ---------------- P3: persistent HMMA-PGD kernel ----------------------------
// 128 CTAs x 256 threads (8 warps); CTA c owns batches (2c, 2c+1).
// KK (fp16, zero-diag) lives in REGISTERS as mma A-fragments: 128 regs/thread.
__global__ void __launch_bounds__(256, 1)
pgd_kernel(const float* __restrict__ alpha_init) {
    __shared__ __half  ys0h[256];
    __shared__ __half  ys1h[256];
    __shared__ float2  Gp[256];
    __shared__ float   redS[16];
    __shared__ float   redN[16];
    __shared__ float   scr[256];

    const int tid  = threadIdx.x;
    const int wid  = tid >> 5;
    const int lane = tid & 31;
    const int gid  = lane >> 2;    // group id (D/B row-or-col index)
    const int tig  = lane & 3;     // thread-in-group
    const int b0 = blockIdx.x * 2;
    const int b1 = b0 + 1;
    const int R  = wid * 32;       // this warp's row base

    // ---- prologue: load A fragments (KK fp16, zero diagonal) into registers
    uint32_t afr[2][16][4];
    #pragma unroll
    for (int mt = 0; mt < 2; ++mt) {
        const int r0 = R + mt * 16 + gid;
        const int r1 = r0 + 8;
        #pragma unroll
        for (int kt = 0; kt < 16; ++kt) {
            const int c = kt * 16 + 2 * tig;
            float v00 = (r0 == c)     ? 0.f : g_K[r0 * 512 + c];
            float v01 = (r0 == c + 1) ? 0.f : g_K[r0 * 512 + c + 1];
            float v10 = (r1 == c)     ? 0.f : g_K[r1 * 512 + c];
            float v11 = (r1 == c + 1) ? 0.f : g_K[r1 * 512 + c + 1];
            float w00 = (r0 == c + 8) ? 0.f : g_K[r0 * 512 + c + 8];
            float w01 = (r0 == c + 9) ? 0.f : g_K[r0 * 512 + c + 9];
            float w10 = (r1 == c + 8) ? 0.f : g_K[r1 * 512 + c + 8];
            float w11 = (r1 == c + 9) ? 0.f : g_K[r1 * 512 + c + 9];
            afr[mt][kt][0] = packh2(v00, v01);
            afr[mt][kt][1] = packh2(v10, v11);
            afr[mt][kt][2] = packh2(w00, w01);
            afr[mt][kt][3] = packh2(w10, w11);
        }
    }

    // fp32 rows b0, b1 of KK (rank-one term), per-thread
    const float rK0 = g_K[b0 * 512 + tid];
    const float rK1 = g_K[b1 * 512 + tid];

    // Per-thread state: thread tid owns scatter slot tid for both batches.
    const bool v0 = (tid != b0), v1 = (tid != b1);
    float a0 = 0.f, ap0 = 0.f, a1 = 0.f, ap1 = 0.f;
    if (v0) { int i0 = tid - (tid > b0); a0 = fminf(fmaxf(alpha_init[b0 * NNK + i0], 0.f), 1.f); ap0 = a0; }
    if (v1) { int i1 = tid - (tid > b1); a1 = fminf(fmaxf(alpha_init[b1 * NNK + i1], 0.f), 1.f); ap1 = a1; }

    // B-fragment load base: column gid of B -> gid==0: ys0, gid==1: ys1, else 0
    const uint32_t* yb = (gid == 1) ? (const uint32_t*)ys1h : (const uint32_t*)ys0h;
    const bool bactive = (gid < 2);

    __syncthreads();

    for (int it = 0; it < NITERS; ++it) {
        float tf = (float)it;
        float beta = tf / (tf + 3.0f);
        float y0 = v0 ? (a0 + beta * (a0 - ap0)) : 0.f;
        float y1 = v1 ? (a1 + beta * (a1 - ap1)) : 0.f;
        ys0h[tid] = __float2half(y0);
        ys1h[tid] = __float2half(y1);

        // warp partials of S = sum(y)
        float s0 = y0, s1 = y1;
        #pragma unroll
        for (int off = 16; off; off >>= 1) {
            s0 += __shfl_xor_sync(0xffffffffu, s0, off);
            s1 += __shfl_xor_sync(0xffffffffu, s1, off);
        }
        if (lane == 0) { redS[wid] = s0; redS[8 + wid] = s1; }
        __syncthreads();                                        // bar 1

        // ---- HMMA matvec: D[32 rows, cols {0:G0, 1:G1}] ----
        float d0[4] = {0.f, 0.f, 0.f, 0.f};
        float d1[4] = {0.f, 0.f, 0.f, 0.f};
        #pragma unroll
        for (int kt = 0; kt < 16; ++kt) {
            uint32_t bf0 = 0u, bf1 = 0u;
            if (bactive) {
                bf0 = yb[kt * 8 + tig];
                bf1 = yb[kt * 8 + tig + 4];
            }
            mma16816(d0, afr[0][kt], bf0, bf1);
            mma16816(d1, afr[1][kt], bf0, bf1);
        }
        // lanes with tig==0 hold cols 0,1 (G0,G1) for rows gid,gid+8 per m-tile
        if (tig == 0) {
            int ra = R + gid;
            Gp[ra]      = make_float2(d0[0], d0[1]);
            Gp[ra + 8]  = make_float2(d0[2], d0[3]);
            Gp[ra + 16] = make_float2(d1[0], d1[1]);
            Gp[ra + 24] = make_float2(d1[2], d1[3]);
        }
        __syncthreads();                                        // bar 2

        float S0 = 0.f, S1 = 0.f;
        #pragma unroll
        for (int w = 0; w < 8; ++w) { S0 += redS[w]; S1 += redS[8 + w]; }
        float2 Gme = Gp[tid];
        float Gb0 = Gp[b0].x;
        float Gb1 = Gp[b1].y;

        // grad = S*(1 - rowK) + 1.1*y + G - G[b] - 2  (diag restored via +y)
        float gv0 = 0.f, gv1 = 0.f;
        if (v0) gv0 = fmaf(1.0f - rK0, S0, fmaf(1.1f, y0, Gme.x - Gb0 - 2.0f));
        if (v1) gv1 = fmaf(1.0f - rK1, S1, fmaf(1.1f, y1, Gme.y - Gb1 - 2.0f));

        float n0 = gv0 * gv0, n1 = gv1 * gv1;
        #pragma unroll
        for (int off = 16; off; off >>= 1) {
            n0 += __shfl_xor_sync(0xffffffffu, n0, off);
            n1 += __shfl_xor_sync(0xffffffffu, n1, off);
        }
        if (lane == 0) { redN[wid] = n0; redN[8 + wid] = n1; }
        __syncthreads();                                        // bar 3

        float N0 = 0.f, N1 = 0.f;
        #pragma unroll
        for (int w = 0; w < 8; ++w) { N0 += redN[w]; N1 += redN[8 + w]; }
        float inv0 = 1.0f / (sqrtf(N0) + 1e-12f);
        float inv1 = 1.0f / (sqrtf(N1) + 1e-12f);

        if (v0) { float an = fminf(fmaxf(y0 - ETA_C * gv0 * inv0, 0.f), 1.f); ap0 = a0; a0 = an; }
        if (v1) { float an = fminf(fmaxf(y1 - ETA_C * gv1 * inv1, 0.f), 1.f); ap1 = a1; a1 = an; }
    }

    // ---- tail: per-batch loss/stat partials ----
    __syncthreads();
    float knt0 = g_K[tid * 512 + 256 + b0];   // Ks[k=tid][b0]
    float knt1 = g_K[tid * 512 + 256 + b1];

    float ax0 = blkred(v0 ? a0 : 0.f, scr, tid);
    float ng0 = blkred(v0 ? a0 * knt0 : 0.f, scr, tid);
    float kt0 = blkred(v0 ? knt0 : 0.f, scr, tid);
    float c10 = blkred((v0 && a0 == 1.0f) ? 1.f : 0.f, scr, tid);
    float cp0 = blkred((v0 && a0 > 0.0f) ? 1.f : 0.f, scr, tid);
    float cz0 = blkred((v0 && a0 == 0.0f) ? 1.f : 0.f, scr, tid);

    float ax1 = blkred(v1 ? a1 : 0.f, scr, tid);
    float ng1 = blkred(v1 ? a1 * knt1 : 0.f, scr, tid);
    float kt1 = blkred(v1 ? knt1 : 0.f, scr, tid);
    float c11 = blkred((v1 && a1 == 1.0f) ? 1.f : 0.f, scr, tid);
    float cp1 = blkred((v1 && a1 > 0.0f) ? 1.f : 0.f, scr, tid);
    float cz1 = blkred((v1 && a1 == 0.0f) ? 1.f : 0.f, scr, tid);

    if (tid == 0) {
        float pos0 = g_K[b0 * 512 + 256 + b0];
        float pos1 = g_K[b1 * 512 + 256 + b1];
        float* P0 = &g_partial[b0 * 8];
        P0[0] = ax0 * pos0; P0[1] = ng0; P0[2] = pos0; P0[3] = kt0;
        P0[4] = c10; P0[5] = cp0; P0[6] = cz0;
        float* P1 = &g_partial[b1 * 8];
        P1[0] = ax1 * pos1; P1[1] = ng1; P1[2] = pos1; P1[3] = kt1;
        P1[4] = c11; P1[5] = cp1; P1[6] = cz1;
    }
}

// ---------------- P4: tiny finisher ----------------------------------------
__global__ void finish_kernel(float* __restrict__ out) {
    __shared__ float red[256];
    int b = threadIdx.x;
    float v0 = g_partial[b * 8 + 0];
    float v1 = g_partial[b * 8 + 1];
    float v2 = g_partial[b * 8 + 2];
    float v3 = g_partial[b * 8 + 3];
    float v4 = g_partial[b * 8 + 4];
    float v5 = g_partial[b * 8 + 5];
    float v6 = g_partial[b * 8 + 6];

    float S0 = blkred(v0, red, b);
    float S1 = blkred(v1, red, b);
    float S2 = blkred(v2, red, b);
    float S3 = blkred(v3, red, b);
    float S4 = blkred(v4, red, b);
    float S5 = blkred(v5, red, b);
    float S6 = blkred(v6, red, b);

    if (b == 0) {
        out[0] = S1 / (float)BSZ - S0 / (float)BSZ;       // neg_loss - pos_loss
        out[1] = S2 / (float)BSZ;                          // pos.mean()
        out[2] = S3 / ((float)BSZ * (float)NNK);           // KnT.mean()
        out[3] = S4 / (S5 + 1e-10f);                       // sparsity
        out[4] = S6 / ((float)BSZ * (float)NNK);           // num_zero
        out[5] = 0.0f;
    }
}

// ---------------- launch ----------------------------------------------------
extern "C" void kernel_launch(void* const* d_in, const int* in_sizes, int n_in,
                              void* d_out, int out_size) {
    const float* z  = (const float*)d_in[0];
    const float* ai = (const float*)d_in[1];
    if (n_in >= 2 && in_sizes[0] == BSZ * NNK && in_sizes[1] == BSZ * 2 * DIM) {
        const float* tmp = z; z = ai; ai = tmp;
    }

    norm_kernel<<<BSZ, DIM>>>(z);
    rbf_kernel_mat<<<BSZ, 256>>>();
    pgd_kernel<<<BSZ / 2, 256>>>(ai);
    finish_kernel<<<1, 256>>>((float*)d_out);
}